// round 1
// baseline (speedup 1.0000x reference)
#include <cuda_runtime.h>
#include <math_constants.h>

// CollectNeighbourAverageAndMax: V=100000, K=32, F=64
// out[v, 0:64]   = sum_k x[idxs[v,k], :] / K
// out[v, 64:128] = max_k x[idxs[v,k], :]
//
// One warp per vertex. Lane l owns features [2l, 2l+1] as float2.
// Neighbor indices loaded coalesced (lane k -> idxs[v*32+k]) and broadcast
// with __shfl_sync. Per neighbor, the 32 lanes read one contiguous 256B row
// slice -> fully coalesced. x (25.6 MB) fits in L2, so steady-state gather
// bandwidth comes from L2, not HBM.

static constexpr int V = 100000;
static constexpr int K = 32;
static constexpr int F = 64;

__global__ __launch_bounds__(256) void collect_nb_kernel(
    const float* __restrict__ x,
    const int* __restrict__ idxs,
    float* __restrict__ out)
{
    const int warp_id = (blockIdx.x * blockDim.x + threadIdx.x) >> 5;
    const int lane = threadIdx.x & 31;
    if (warp_id >= V) return;

    // Coalesced index load: lane k holds idxs[v*K + k]
    const int my_idx = idxs[warp_id * K + lane];

    float2 s = make_float2(0.0f, 0.0f);
    float2 m = make_float2(-CUDART_INF_F, -CUDART_INF_F);

    #pragma unroll
    for (int k = 0; k < K; ++k) {
        const int nb = __shfl_sync(0xffffffffu, my_idx, k);
        const float2 v = *reinterpret_cast<const float2*>(
            x + (size_t)nb * F + 2 * lane);
        s.x += v.x;
        s.y += v.y;
        m.x = fmaxf(m.x, v.x);
        m.y = fmaxf(m.y, v.y);
    }

    s.x *= (1.0f / K);
    s.y *= (1.0f / K);

    float* o = out + (size_t)warp_id * (2 * F);
    *reinterpret_cast<float2*>(o + 2 * lane) = s;           // mean part
    *reinterpret_cast<float2*>(o + F + 2 * lane) = m;       // max part
}

extern "C" void kernel_launch(void* const* d_in, const int* in_sizes, int n_in,
                              void* d_out, int out_size)
{
    const float* x = (const float*)d_in[0];
    const int* idxs = (const int*)d_in[1];
    float* out = (float*)d_out;

    const int threads = 256;                  // 8 warps -> 8 vertices per block
    const int warps_per_block = threads / 32;
    const int blocks = (V + warps_per_block - 1) / warps_per_block;  // 12500

    collect_nb_kernel<<<blocks, threads>>>(x, idxs, out);
}